// round 16
// baseline (speedup 1.0000x reference)
#include <cuda_runtime.h>
#include <math.h>
#include <stdint.h>

// ---------------- problem constants ----------------
#define B    128
#define NP   1024
#define NN   (B*NP)        // 131072 nodes
#define H    128
#define C    10
#define DEG  16
#define NE   (NN*DEG)      // 2097152 edges
#define K1   820
#define K2   656
#define K3   525

#define TS   36
#define TILE_U32 (128*TS)   // 4608 u32 = one 128x32 padded tf32 tile

// ---------------- device scratch (no mallocs allowed) ----------------
__device__ float g_x[(size_t)NN*H];     // node features for layers >= 2 (layer 1 reads input x)
__device__ float g_h[(size_t)NN*H];     // SAGE+ReLU output
__device__ float g_score[NN];
__device__ unsigned char g_nm[NN];      // node alive mask
__device__ int  g_liveA[NN];            // per-graph live lists (stride NP)
__device__ int  g_liveB[NN];
__device__ int  g_deg[NN];
__device__ int  g_rowptr[NN+1];
__device__ int  g_cursor[NN];
__device__ int  g_cols[NE];
__device__ int  g_bs[128];
__device__ float g_invwp[3];
// pre-split tf32 W images: [layer][chunk][kb(4)][hi 4608 | lo 4608]
__device__ uint32_t g_wimg[3*2*4*2*TILE_U32];

// ---------------- setup kernels ----------------
__global__ void k_init() {
    int i = blockIdx.x*blockDim.x + threadIdx.x;
    if (i < NN) { g_nm[i] = 1; g_deg[i] = 0; }
}
__global__ void k_count(const int* __restrict__ dst) {
    int e = blockIdx.x*blockDim.x + threadIdx.x;
    if (e < NE) atomicAdd(&g_deg[dst[e]], 1);
}
__global__ void k_scan1() {
    __shared__ int s[1024];
    int i = blockIdx.x*1024 + threadIdx.x;
    int v = g_deg[i];
    s[threadIdx.x] = v;
    __syncthreads();
    for (int off = 1; off < 1024; off <<= 1) {
        int t = (threadIdx.x >= off) ? s[threadIdx.x - off] : 0;
        __syncthreads();
        s[threadIdx.x] += t;
        __syncthreads();
    }
    g_rowptr[i] = s[threadIdx.x] - v;
    if (threadIdx.x == 1023) g_bs[blockIdx.x] = s[1023];
}
// merged scan2+scan3: each block computes its own offset over g_bs in-block
__global__ void k_scan23() {
    __shared__ int sb[128];
    __shared__ int off;
    if (threadIdx.x < 128) sb[threadIdx.x] = g_bs[threadIdx.x];
    __syncthreads();
    if (threadIdx.x == 0) {
        int acc = 0;
        int bid = blockIdx.x;
        for (int t = 0; t < bid; t++) acc += sb[t];
        off = acc;
    }
    __syncthreads();
    int i = blockIdx.x*1024 + threadIdx.x;
    int v = g_rowptr[i] + off;
    g_rowptr[i] = v;
    g_cursor[i] = v;
    if (i == 0) g_rowptr[NN] = NE;
}
__global__ void k_fill(const int* __restrict__ src, const int* __restrict__ dst) {
    int e = blockIdx.x*blockDim.x + threadIdx.x;
    if (e < NE) {
        int pos = atomicAdd(&g_cursor[dst[e]], 1);
        g_cols[pos] = src[e];
    }
}
// all three wp norms in one launch (block b handles wp_b)
__global__ void k_wpnorm3(const float* __restrict__ wpA, const float* __restrict__ wpB,
                          const float* __restrict__ wpC) {
    __shared__ float s[128];
    const float* wp = (blockIdx.x == 0) ? wpA : (blockIdx.x == 1) ? wpB : wpC;
    float v = wp[threadIdx.x];
    s[threadIdx.x] = v*v;
    __syncthreads();
    for (int o = 64; o > 0; o >>= 1) {
        if (threadIdx.x < o) s[threadIdx.x] += s[threadIdx.x + o];
        __syncthreads();
    }
    if (threadIdx.x == 0) g_invwp[blockIdx.x] = 1.0f/(sqrtf(s[0]) + 1e-16f);
}

// ---------------- tf32 helpers ----------------
__device__ __forceinline__ uint32_t f2tf32(float x) {
    uint32_t r;
    asm("cvt.rna.tf32.f32 %0, %1;" : "=r"(r) : "f"(x));
    return r;
}
__device__ __forceinline__ void mma_tf32(float* d, const uint32_t* a, const uint32_t* b) {
    asm volatile("mma.sync.aligned.m16n8k8.row.col.f32.tf32.tf32.f32 "
        "{%0,%1,%2,%3}, {%4,%5,%6,%7}, {%8,%9}, {%0,%1,%2,%3};"
        : "+f"(d[0]), "+f"(d[1]), "+f"(d[2]), "+f"(d[3])
        : "r"(a[0]), "r"(a[1]), "r"(a[2]), "r"(a[3]), "r"(b[0]), "r"(b[1]));
}
__device__ __forceinline__ uint32_t smem_addr_u32(const void* p) {
    return (uint32_t)__cvta_generic_to_shared(p);
}
__device__ __forceinline__ void cp_async16(uint32_t sdst, const void* gsrc) {
    asm volatile("cp.async.cg.shared.global [%0], [%1], 16;" :: "r"(sdst), "l"(gsrc) : "memory");
}
__device__ __forceinline__ void cp_async_commit_wait() {
    asm volatile("cp.async.commit_group;" ::: "memory");
    asm volatile("cp.async.wait_group 0;" ::: "memory");
}

// ---------------- pre-split ALL W matrices in one launch ----------------
__global__ void k_wsplit6(const float* __restrict__ Wl1, const float* __restrict__ Wr1,
                          const float* __restrict__ Wl2, const float* __restrict__ Wr2,
                          const float* __restrict__ Wl3, const float* __restrict__ Wr3) {
    int gidx = blockIdx.x*blockDim.x + threadIdx.x;     // 0..98303
    int which = gidx >> 14;                             // 0..5
    int idx = gidx & 16383;
    const float* W =
        (which == 0) ? Wl1 : (which == 1) ? Wr1 :
        (which == 2) ? Wl2 : (which == 3) ? Wr2 :
        (which == 4) ? Wl3 : Wr3;
    int n = idx >> 7, k = idx & 127;
    float a = W[idx];
    uint32_t hi = f2tf32(a);
    float lo = a - __uint_as_float(hi);
    uint32_t* img = g_wimg + (size_t)which*(8*TILE_U32) + (size_t)(k >> 5)*(2*TILE_U32);
    int kc = k & 31;
    img[n*TS + kc]            = hi;
    img[TILE_U32 + n*TS + kc] = f2tf32(lo);
}

// ================= tf32 split-precision HMMA GEMM with FUSED mean gather =================
// chunk 0 (mean): gathered + averaged + split in-staging (k_agg deleted; bit-identical order)
// chunk 1 (x):    A staged via LDG + cvt
// dynamic smem: [sA_hi | sA_lo | sW(hi|lo) | snode(128) | sb(128) | swp(128)]
#define SMEM_GEMM ((4*TILE_U32)*4 + 128*4*3)

__global__ void __launch_bounds__(256, 2)
k_gemm_mma(int livesel, int kkprev, int layer, const float* __restrict__ xin,
           const float* __restrict__ bl, const float* __restrict__ wp) {
    extern __shared__ uint32_t sm[];
    uint32_t* sA_hi = sm;
    uint32_t* sA_lo = sm + TILE_U32;
    uint32_t* sW    = sm + 2*TILE_U32;     // [hi 4608 | lo 4608]
    int*   snode = (int*)(sm + 4*TILE_U32);
    float* sb    = (float*)(sm + 4*TILE_U32 + 128);
    float* swp   = (float*)(sm + 4*TILE_U32 + 256);

    const int* live = (livesel == 1) ? g_liveA : (livesel == 2) ? g_liveB : nullptr;
    int tid = threadIdx.x;
    int wid = tid >> 5, lane = tid & 31;
    int lq = lane >> 2, lr = lane & 3;
    uint32_t sW_sh = smem_addr_u32(sW) + tid*16;

    if (tid < 128) {
        int r = blockIdx.x * 128 + tid;
        int node;
        if (live) { int b = r / kkprev; node = live[b*NP + (r - b*kkprev)]; }
        else node = r;
        snode[tid] = node;
        sb[tid]  = bl[tid];
        swp[tid] = wp[tid] * g_invwp[layer];
    }

    float d[16][4];
    #pragma unroll
    for (int i = 0; i < 16; i++)
        #pragma unroll
        for (int j = 0; j < 4; j++) d[i][j] = 0.f;
    __syncthreads();   // snode ready (needed by chunk-0 gather below)

    // gather row assignment: 2 threads per row, each covers 16 k
    int grow  = tid >> 1;
    int ghalf = tid & 1;
    int gnode = snode[grow];
    int gs = g_rowptr[gnode], ge = g_rowptr[gnode+1];

    const float* Asrc = (livesel == 0) ? xin : g_x;

    for (int chunk = 0; chunk < 2; chunk++) {
        const uint32_t* wbase = g_wimg + (size_t)(layer*2 + chunk)*(8*TILE_U32);
        for (int kb = 0; kb < 128; kb += 32) {
            __syncthreads();     // previous iteration's reads done
            // ---- stage W early via cp.async ----
            {
                const uint4* wsrc = (const uint4*)(wbase + (size_t)(kb >> 5)*(2*TILE_U32)) + tid;
                #pragma unroll
                for (int i = 0; i < 9; i++)
                    cp_async16(sW_sh + i*4096, wsrc + i*256);
            }
            if (chunk == 0) {
                // ---- FUSED mean gather: this thread computes mean[grow][kb+ghalf*16 .. +16) ----
                float4 a0 = make_float4(0.f,0.f,0.f,0.f), a1 = a0, a2 = a0, a3 = a0;
                int cnt = 0;
                const float* xk = Asrc + kb + ghalf*16;
                for (int p = gs; p < ge; p++) {
                    int j = g_cols[p];
                    cnt += g_nm[j];
                    const float4* src = (const float4*)(xk + (size_t)j*H);
                    float4 v0 = src[0], v1 = src[1], v2 = src[2], v3 = src[3];
                    a0.x += v0.x; a0.y += v0.y; a0.z += v0.z; a0.w += v0.w;
                    a1.x += v1.x; a1.y += v1.y; a1.z += v1.z; a1.w += v1.w;
                    a2.x += v2.x; a2.y += v2.y; a2.z += v2.z; a2.w += v2.w;
                    a3.x += v3.x; a3.y += v3.y; a3.z += v3.z; a3.w += v3.w;
                }
                if (livesel == 0) cnt = ge - gs;
                float inv = 1.0f / (float)max(cnt, 1);
                int o = grow*TS + ghalf*16;
                float4 av[4] = {a0, a1, a2, a3};
                #pragma unroll
                for (int g = 0; g < 4; g++) {
                    float m0 = av[g].x*inv, m1 = av[g].y*inv, m2 = av[g].z*inv, m3 = av[g].w*inv;
                    uint32_t h0 = f2tf32(m0), h1 = f2tf32(m1), h2 = f2tf32(m2), h3 = f2tf32(m3);
                    uint32_t l0 = f2tf32(m0 - __uint_as_float(h0));
                    uint32_t l1 = f2tf32(m1 - __uint_as_float(h1));
                    uint32_t l2 = f2tf32(m2 - __uint_as_float(h2));
                    uint32_t l3 = f2tf32(m3 - __uint_as_float(h3));
                    *(uint4*)(sA_hi + o + g*4) = make_uint4(h0, h1, h2, h3);
                    *(uint4*)(sA_lo + o + g*4) = make_uint4(l0, l1, l2, l3);
                }
            } else {
                // ---- stage A: 128 rows x 32 k, fp32 -> tf32 hi/lo ----
                #pragma unroll
                for (int i = 0; i < 4; i++) {
                    int f = i*256 + tid;
                    int row = f >> 3, kc = (f & 7) * 4;
                    int node = snode[row];
                    float4 v = *(const float4*)(Asrc + (size_t)node*H + kb + kc);
                    uint32_t hi[4]; float lo[4];
                    float* e = &v.x;
                    #pragma unroll
                    for (int q = 0; q < 4; q++) {
                        hi[q] = f2tf32(e[q]);
                        lo[q] = e[q] - __uint_as_float(hi[q]);
                    }
                    int o = row*TS + kc;
                    *(uint4*)(sA_hi + o) = make_uint4(hi[0], hi[1], hi[2], hi[3]);
                    *(uint4*)(sA_lo + o) = make_uint4(f2tf32(lo[0]), f2tf32(lo[1]),
                                                      f2tf32(lo[2]), f2tf32(lo[3]));
                }
            }
            cp_async_commit_wait();
            __syncthreads();

            uint32_t* sW_hi = sW;
            uint32_t* sW_lo = sW + TILE_U32;

            // ---- MMA: warp covers rows [wid*16, wid*16+16) x cols [0,128) ----
            #pragma unroll
            for (int ks = 0; ks < 4; ks++) {
                int kk = ks*8 + lr;
                int row = wid*16 + lq;
                uint32_t a_hi[4], a_lo[4];
                a_hi[0] = sA_hi[row*TS + kk];
                a_hi[1] = sA_hi[(row+8)*TS + kk];
                a_hi[2] = sA_hi[row*TS + kk + 4];
                a_hi[3] = sA_hi[(row+8)*TS + kk + 4];
                a_lo[0] = sA_lo[row*TS + kk];
                a_lo[1] = sA_lo[(row+8)*TS + kk];
                a_lo[2] = sA_lo[row*TS + kk + 4];
                a_lo[3] = sA_lo[(row+8)*TS + kk + 4];
                #pragma unroll
                for (int nf = 0; nf < 16; nf++) {
                    int col = nf*8 + lq;
                    uint32_t b_hi[2], b_lo[2];
                    b_hi[0] = sW_hi[col*TS + kk];
                    b_hi[1] = sW_hi[col*TS + kk + 4];
                    b_lo[0] = sW_lo[col*TS + kk];
                    b_lo[1] = sW_lo[col*TS + kk + 4];
                    mma_tf32(d[nf], a_hi, b_hi);
                    mma_tf32(d[nf], a_lo, b_hi);
                    mma_tf32(d[nf], a_hi, b_lo);
                }
            }
        }
    }

    // ---- epilogue: bias + relu, write h, per-row deterministic score ----
    int r0 = wid*16 + lq;        // and r0+8
    int n0 = snode[r0], n1 = snode[r0+8];
    float* hp0 = g_h + (size_t)n0*H;
    float* hp1 = g_h + (size_t)n1*H;
    float s0 = 0.f, s1 = 0.f;
    #pragma unroll
    for (int nf = 0; nf < 16; nf++) {
        int col = nf*8 + lr*2;
        float w0 = swp[col], w1 = swp[col+1];
        float b0 = sb[col],  b1 = sb[col+1];
        float h00 = fmaxf(d[nf][0] + b0, 0.f);
        float h01 = fmaxf(d[nf][1] + b1, 0.f);
        float h10 = fmaxf(d[nf][2] + b0, 0.f);
        float h11 = fmaxf(d[nf][3] + b1, 0.f);
        s0 += h00*w0 + h01*w1;
        s1 += h10*w0 + h11*w1;
        *(float2*)(hp0 + col) = make_float2(h00, h01);
        *(float2*)(hp1 + col) = make_float2(h10, h11);
    }
    s0 += __shfl_xor_sync(0xFFFFFFFF, s0, 1);
    s0 += __shfl_xor_sync(0xFFFFFFFF, s0, 2);
    s1 += __shfl_xor_sync(0xFFFFFFFF, s1, 1);
    s1 += __shfl_xor_sync(0xFFFFFFFF, s1, 2);
    if (lr == 0) {
        g_score[n0] = s0;
        g_score[n1] = s1;
    }
}

// ---------------- per-graph top-k; gate selected x, ZERO pruned x ----------------
__global__ void k_topk(int livesel_in, int mlive, int kk, int livesel_out) {
    const int* live_in = (livesel_in == 1) ? g_liveA : (livesel_in == 2) ? g_liveB : nullptr;
    int* live_out = (livesel_out == 1) ? g_liveA : g_liveB;
    __shared__ unsigned long long keys[1024];
    __shared__ float gates[1024];
    int b = blockIdx.x;
    int tid = threadIdx.x;   // 512 threads

    for (int t = tid; t < 1024; t += 512) {
        unsigned long long key = 0xFFFFFFFFFFFFFFFFULL;
        if (t < mlive) {
            int node = live_in ? live_in[b*NP + t] : (b*NP + t);
            unsigned int p = (unsigned int)(node - b*NP);
            float s = g_score[node];
            unsigned int u = __float_as_uint(s);
            u = (u & 0x80000000u) ? ~u : (u | 0x80000000u);
            key = (((unsigned long long)(~u)) << 32) | p;
        }
        keys[t] = key;
    }
    __syncthreads();

    for (int k = 2; k <= 1024; k <<= 1) {
        for (int j = k >> 1; j > 0; j >>= 1) {
            for (int t = tid; t < 1024; t += 512) {
                int l = t ^ j;
                if (l > t) {
                    bool asc = ((t & k) == 0);
                    unsigned long long a = keys[t], c2 = keys[l];
                    if ((a > c2) == asc) { keys[t] = c2; keys[l] = a; }
                }
            }
            __syncthreads();
        }
    }

    for (int t = tid; t < NP; t += 512) g_nm[b*NP + t] = 0;
    __syncthreads();
    for (int s = tid; s < kk; s += 512) {
        unsigned int p = (unsigned int)(keys[s] & 0xFFFFFFFFu);
        int node = b*NP + (int)p;
        g_nm[node] = 1;
        live_out[b*NP + s] = node;
        gates[s] = tanhf(g_score[node]);
    }
    __syncthreads();
    // gate selected rows
    for (int w = tid; w < kk*32; w += 512) {
        int s = w >> 5, f = w & 31;
        unsigned int p = (unsigned int)(keys[s] & 0xFFFFFFFFu);
        int node = b*NP + (int)p;
        float4 hv = ((const float4*)(g_h + (size_t)node*H))[f];
        float g = gates[s];
        ((float4*)(g_x + (size_t)node*H))[f] =
            make_float4(hv.x*g, hv.y*g, hv.z*g, hv.w*g);
    }
    // zero rows alive-before-but-pruned-now so dense gathers stay exact
    int nz = mlive - kk;
    for (int w = tid; w < nz*32; w += 512) {
        int s = kk + (w >> 5), f = w & 31;
        unsigned int p = (unsigned int)(keys[s] & 0xFFFFFFFFu);
        int node = b*NP + (int)p;
        ((float4*)(g_x + (size_t)node*H))[f] = make_float4(0.f, 0.f, 0.f, 0.f);
    }
}

// ---------------- mean pool + MLP + log_softmax (parallelized) ----------------
__global__ void k_mlp(int livesel, const float* __restrict__ Wf1, const float* __restrict__ bf1,
                      const float* __restrict__ Wf2, const float* __restrict__ bf2,
                      float* __restrict__ out) {
    const int* live = (livesel == 1) ? g_liveA : g_liveB;
    __shared__ float pool4[4][128];
    __shared__ float pooled[128];
    __shared__ float h1p[8][64];
    __shared__ float h1[64];
    __shared__ float o10[10];
    int b = blockIdx.x, tid = threadIdx.x;   // 512 threads
    int d = tid & 127, q = tid >> 7;          // q in 0..3
    float s = 0.f;
    for (int i = q; i < K3; i += 4) {
        int node = live[b*NP + i];
        s += g_x[(size_t)node*H + d];
    }
    pool4[q][d] = s;
    __syncthreads();
    if (tid < 128) {
        pooled[tid] = (pool4[0][tid] + pool4[1][tid] + pool4[2][tid] + pool4[3][tid])
                      * (1.0f/(float)K3);
    }
    __syncthreads();
    {
        int dd = tid & 63, qq = tid >> 6;     // qq in 0..7, 16 k's each
        float a = 0.f;
        #pragma unroll
        for (int k = 0; k < 16; k++)
            a += pooled[qq*16 + k] * Wf1[dd*128 + qq*16 + k];
        h1p[qq][dd] = a;
    }
    __syncthreads();
    if (tid < 64) {
        float a = bf1[tid];
        #pragma unroll
        for (int qq = 0; qq < 8; qq++) a += h1p[qq][tid];
        h1[tid] = fmaxf(a, 0.f);
    }
    __syncthreads();
    if (tid < 10) {
        float a = bf2[tid];
        for (int k = 0; k < 64; k++) a += h1[k] * Wf2[tid*64 + k];
        o10[tid] = a;
    }
    __syncthreads();
    if (tid == 0) {
        float m = -1e30f;
        for (int c = 0; c < C; c++) m = fmaxf(m, o10[c]);
        float se = 0.f;
        for (int c = 0; c < C; c++) se += expf(o10[c] - m);
        float lse = m + logf(se);
        for (int c = 0; c < C; c++) out[b*C + c] = o10[c] - lse;
    }
}

// ---------------- launch ----------------
extern "C" void kernel_launch(void* const* d_in, const int* in_sizes, int n_in,
                              void* d_out, int out_size) {
    const float* x   = (const float*)d_in[0];
    const int*   ei  = (const int*)  d_in[1];
    const float* Wl1 = (const float*)d_in[2];
    const float* bl1 = (const float*)d_in[3];
    const float* Wr1 = (const float*)d_in[4];
    const float* wp1 = (const float*)d_in[5];
    const float* Wl2 = (const float*)d_in[6];
    const float* bl2 = (const float*)d_in[7];
    const float* Wr2 = (const float*)d_in[8];
    const float* wp2 = (const float*)d_in[9];
    const float* Wl3 = (const float*)d_in[10];
    const float* bl3 = (const float*)d_in[11];
    const float* Wr3 = (const float*)d_in[12];
    const float* wp3 = (const float*)d_in[13];
    const float* Wf1 = (const float*)d_in[14];
    const float* bf1 = (const float*)d_in[15];
    const float* Wf2 = (const float*)d_in[16];
    const float* bf2 = (const float*)d_in[17];
    float* out = (float*)d_out;

    const int* srcp = ei;
    const int* dstp = ei + NE;

    cudaFuncSetAttribute(k_gemm_mma, cudaFuncAttributeMaxDynamicSharedMemorySize, SMEM_GEMM);

    // CSR build + consolidated setup
    k_init   <<<(NN + 255)/256, 256>>>();
    k_count  <<<(NE + 255)/256, 256>>>(dstp);
    k_scan1  <<<128, 1024>>>();
    k_scan23 <<<128, 1024>>>();
    k_fill   <<<(NE + 255)/256, 256>>>(srcp, dstp);
    k_wsplit6<<<384, 256>>>(Wl1, Wr1, Wl2, Wr2, Wl3, Wr3);
    k_wpnorm3<<<3, 128>>>(wp1, wp2, wp3);

    // layer 1 (all nodes live): 1024 tiles, mean fused into GEMM
    k_gemm_mma<<<NN/128, 256, SMEM_GEMM>>>(0, 1, 0, x, bl1, wp1);
    k_topk    <<<B, 512>>>(0, NP, K1, 1);

    // layer 2 (live list A, K1 per graph): 820 tiles
    k_gemm_mma<<<(B*K1)/128, 256, SMEM_GEMM>>>(1, K1, 1, x, bl2, wp2);
    k_topk    <<<B, 512>>>(1, K1, K2, 2);

    // layer 3 (live list B, K2 per graph): 656 tiles
    k_gemm_mma<<<(B*K2)/128, 256, SMEM_GEMM>>>(2, K2, 2, x, bl3, wp3);
    k_topk    <<<B, 512>>>(2, K2, K3, 1);

    // pool + MLP + log_softmax
    k_mlp<<<B, 512>>>(1, Wf1, bf1, Wf2, bf2, out);
}

// round 17
// speedup vs baseline: 1.2721x; 1.2721x over previous
#include <cuda_runtime.h>
#include <math.h>
#include <stdint.h>

// ---------------- problem constants ----------------
#define B    128
#define NP   1024
#define NN   (B*NP)        // 131072 nodes
#define H    128
#define C    10
#define DEG  16
#define NE   (NN*DEG)      // 2097152 edges
#define K1   820
#define K2   656
#define K3   525

#define TS   36
#define TILE_U32 (128*TS)   // 4608 u32 = one 128x32 padded tf32 tile

// ---------------- device scratch (no mallocs allowed) ----------------
__device__ float g_x[(size_t)NN*H];     // node features for layers >= 2 (layer 1 reads input x)
__device__ float g_h[(size_t)NN*H];     // SAGE+ReLU output
__device__ float g_score[NN];
__device__ unsigned char g_nm[NN];      // node alive mask
__device__ int  g_liveA[NN];            // per-graph live lists (stride NP)
__device__ int  g_liveB[NN];
__device__ int  g_deg[NN];
__device__ int  g_rowptr[NN+1];
__device__ int  g_cursor[NN];
__device__ int  g_cols[NE];
__device__ int  g_bs[128];
__device__ float g_invwp[3];
// pre-split tf32 W images: [layer][chunk][kb(4)][hi 4608 | lo 4608]
__device__ uint32_t g_wimg[3*2*4*2*TILE_U32];
// pre-split tf32 mean: per node [kb(4)][hi 32 u32 | lo 32 u32] = 256 u32
__device__ uint32_t g_means[(size_t)NN*256];

// ---------------- setup kernels ----------------
__global__ void k_init() {
    int i = blockIdx.x*blockDim.x + threadIdx.x;
    if (i < NN) { g_nm[i] = 1; g_deg[i] = 0; }
}
__global__ void k_count(const int* __restrict__ dst) {
    int e = blockIdx.x*blockDim.x + threadIdx.x;
    if (e < NE) atomicAdd(&g_deg[dst[e]], 1);
}
__global__ void k_scan1() {
    __shared__ int s[1024];
    int i = blockIdx.x*1024 + threadIdx.x;
    int v = g_deg[i];
    s[threadIdx.x] = v;
    __syncthreads();
    for (int off = 1; off < 1024; off <<= 1) {
        int t = (threadIdx.x >= off) ? s[threadIdx.x - off] : 0;
        __syncthreads();
        s[threadIdx.x] += t;
        __syncthreads();
    }
    g_rowptr[i] = s[threadIdx.x] - v;
    if (threadIdx.x == 1023) g_bs[blockIdx.x] = s[1023];
}
// merged scan2+scan3: each block computes its own offset over g_bs in-block
__global__ void k_scan23() {
    __shared__ int sb[128];
    __shared__ int off;
    if (threadIdx.x < 128) sb[threadIdx.x] = g_bs[threadIdx.x];
    __syncthreads();
    if (threadIdx.x == 0) {
        int acc = 0;
        int bid = blockIdx.x;
        for (int t = 0; t < bid; t++) acc += sb[t];
        off = acc;
    }
    __syncthreads();
    int i = blockIdx.x*1024 + threadIdx.x;
    int v = g_rowptr[i] + off;
    g_rowptr[i] = v;
    g_cursor[i] = v;
    if (i == 0) g_rowptr[NN] = NE;
}
__global__ void k_fill(const int* __restrict__ src, const int* __restrict__ dst) {
    int e = blockIdx.x*blockDim.x + threadIdx.x;
    if (e < NE) {
        int pos = atomicAdd(&g_cursor[dst[e]], 1);
        g_cols[pos] = src[e];
    }
}
// all three wp norms in one launch (block b handles wp_b)
__global__ void k_wpnorm3(const float* __restrict__ wpA, const float* __restrict__ wpB,
                          const float* __restrict__ wpC) {
    __shared__ float s[128];
    const float* wp = (blockIdx.x == 0) ? wpA : (blockIdx.x == 1) ? wpB : wpC;
    float v = wp[threadIdx.x];
    s[threadIdx.x] = v*v;
    __syncthreads();
    for (int o = 64; o > 0; o >>= 1) {
        if (threadIdx.x < o) s[threadIdx.x] += s[threadIdx.x + o];
        __syncthreads();
    }
    if (threadIdx.x == 0) g_invwp[blockIdx.x] = 1.0f/(sqrtf(s[0]) + 1e-16f);
}

// ---------------- tf32 helpers ----------------
__device__ __forceinline__ uint32_t f2tf32(float x) {
    uint32_t r;
    asm("cvt.rna.tf32.f32 %0, %1;" : "=r"(r) : "f"(x));
    return r;
}
__device__ __forceinline__ void mma_tf32(float* d, const uint32_t* a, const uint32_t* b) {
    asm volatile("mma.sync.aligned.m16n8k8.row.col.f32.tf32.tf32.f32 "
        "{%0,%1,%2,%3}, {%4,%5,%6,%7}, {%8,%9}, {%0,%1,%2,%3};"
        : "+f"(d[0]), "+f"(d[1]), "+f"(d[2]), "+f"(d[3])
        : "r"(a[0]), "r"(a[1]), "r"(a[2]), "r"(a[3]), "r"(b[0]), "r"(b[1]));
}
__device__ __forceinline__ uint32_t smem_addr_u32(const void* p) {
    return (uint32_t)__cvta_generic_to_shared(p);
}
__device__ __forceinline__ void cp_async16(uint32_t sdst, const void* gsrc) {
    asm volatile("cp.async.cg.shared.global [%0], [%1], 16;" :: "r"(sdst), "l"(gsrc) : "memory");
}
__device__ __forceinline__ void cp_async_commit_wait() {
    asm volatile("cp.async.commit_group;" ::: "memory");
    asm volatile("cp.async.wait_group 0;" ::: "memory");
}

// ---------------- pre-split ALL W matrices in one launch ----------------
__global__ void k_wsplit6(const float* __restrict__ Wl1, const float* __restrict__ Wr1,
                          const float* __restrict__ Wl2, const float* __restrict__ Wr2,
                          const float* __restrict__ Wl3, const float* __restrict__ Wr3) {
    int gidx = blockIdx.x*blockDim.x + threadIdx.x;     // 0..98303
    int which = gidx >> 14;                             // 0..5
    int idx = gidx & 16383;
    const float* W =
        (which == 0) ? Wl1 : (which == 1) ? Wr1 :
        (which == 2) ? Wl2 : (which == 3) ? Wr2 :
        (which == 4) ? Wl3 : Wr3;
    int n = idx >> 7, k = idx & 127;
    float a = W[idx];
    uint32_t hi = f2tf32(a);
    float lo = a - __uint_as_float(hi);
    uint32_t* img = g_wimg + (size_t)which*(8*TILE_U32) + (size_t)(k >> 5)*(2*TILE_U32);
    int kc = k & 31;
    img[n*TS + kc]            = hi;
    img[TILE_U32 + n*TS + kc] = f2tf32(lo);
}

// ---------------- SAGE mean aggregation: one warp per live dst ----------------
// writes the mean directly in tf32 hi/lo split form (GEMM is the only consumer)
__global__ void k_agg(int livesel, int kkprev, int M, const float* __restrict__ xin) {
    const int* live = (livesel == 1) ? g_liveA : (livesel == 2) ? g_liveB : nullptr;
    const float* xsrc = live ? g_x : xin;
    int w = (blockIdx.x*blockDim.x + threadIdx.x) >> 5;
    int lane = threadIdx.x & 31;
    if (w >= M) return;
    int node;
    if (live) { int b = w / kkprev; node = live[b*NP + (w - b*kkprev)]; }
    else node = w;
    int s = g_rowptr[node], e = g_rowptr[node+1];
    float4 acc = make_float4(0.f, 0.f, 0.f, 0.f);
    int cnt;
    if (!live) {
        cnt = e - s;                      // layer 1: all neighbors alive
        for (int p = s; p < e; p++) {
            int j = g_cols[p];
            float4 v = ((const float4*)(xsrc + (size_t)j*H))[lane];
            acc.x += v.x; acc.y += v.y; acc.z += v.z; acc.w += v.w;
        }
    } else {
        cnt = 0;                          // dead rows are zero -> gather unconditionally
        for (int p = s; p < e; p++) {
            int j = g_cols[p];
            cnt += g_nm[j];
            float4 v = ((const float4*)(xsrc + (size_t)j*H))[lane];
            acc.x += v.x; acc.y += v.y; acc.z += v.z; acc.w += v.w;
        }
    }
    float inv = 1.0f / (float)max(cnt, 1);
    float m[4] = {acc.x*inv, acc.y*inv, acc.z*inv, acc.w*inv};
    uint32_t hi[4], lo[4];
    #pragma unroll
    for (int q = 0; q < 4; q++) {
        hi[q] = f2tf32(m[q]);
        lo[q] = f2tf32(m[q] - __uint_as_float(hi[q]));
    }
    // layout: per node [kb][hi 32 | lo 32]; lane covers kc = lane*4
    uint32_t* dst = g_means + (size_t)node*256 + (lane >> 3)*64 + (lane & 7)*4;
    *(uint4*)dst        = make_uint4(hi[0], hi[1], hi[2], hi[3]);
    *(uint4*)(dst + 32) = make_uint4(lo[0], lo[1], lo[2], lo[3]);
}

// ================= tf32 split-precision HMMA GEMM =================
// chunk 0 (mean): A staged by pure cp.async from pre-split g_means (16 segs/row)
// chunk 1 (x):    A staged via LDG + cvt (x kept fp32 for gather/mlp)
// dynamic smem: [sA_hi | sA_lo | sW(hi|lo) | snode(128) | sb(128) | swp(128)]
#define SMEM_GEMM ((4*TILE_U32)*4 + 128*4*3)

__global__ void __launch_bounds__(256, 2)
k_gemm_mma(int livesel, int kkprev, int layer, const float* __restrict__ xin,
           const float* __restrict__ bl, const float* __restrict__ wp) {
    extern __shared__ uint32_t sm[];
    uint32_t* sA_hi = sm;
    uint32_t* sA_lo = sm + TILE_U32;
    uint32_t* sW    = sm + 2*TILE_U32;     // [hi 4608 | lo 4608]
    int*   snode = (int*)(sm + 4*TILE_U32);
    float* sb    = (float*)(sm + 4*TILE_U32 + 128);
    float* swp   = (float*)(sm + 4*TILE_U32 + 256);

    const int* live = (livesel == 1) ? g_liveA : (livesel == 2) ? g_liveB : nullptr;
    int tid = threadIdx.x;
    int wid = tid >> 5, lane = tid & 31;
    int lq = lane >> 2, lr = lane & 3;
    uint32_t sW_sh   = smem_addr_u32(sW) + tid*16;
    uint32_t sAhi_sh = smem_addr_u32(sA_hi);
    uint32_t sAlo_sh = smem_addr_u32(sA_lo);

    if (tid < 128) {
        int r = blockIdx.x * 128 + tid;
        int node;
        if (live) { int b = r / kkprev; node = live[b*NP + (r - b*kkprev)]; }
        else node = r;
        snode[tid] = node;
        sb[tid]  = bl[tid];
        swp[tid] = wp[tid] * g_invwp[layer];
    }

    float d[16][4];
    #pragma unroll
    for (int i = 0; i < 16; i++)
        #pragma unroll
        for (int j = 0; j < 4; j++) d[i][j] = 0.f;

    for (int chunk = 0; chunk < 2; chunk++) {
        const float* Asrc = (livesel == 0) ? xin : g_x;   // used by chunk 1 only
        const uint32_t* wbase = g_wimg + (size_t)(layer*2 + chunk)*(8*TILE_U32);
        for (int kb = 0; kb < 128; kb += 32) {
            __syncthreads();     // previous iteration's reads done
            // ---- stage W early via cp.async ----
            {
                const uint4* wsrc = (const uint4*)(wbase + (size_t)(kb >> 5)*(2*TILE_U32)) + tid;
                #pragma unroll
                for (int i = 0; i < 9; i++)
                    cp_async16(sW_sh + i*4096, wsrc + i*256);
            }
            if (chunk == 0) {
                // ---- stage A via cp.async from pre-split g_means ----
                // 128 rows x 16 segments (8 hi + 8 lo) of 16B each = 2048 copies
                #pragma unroll
                for (int i = 0; i < 8; i++) {
                    int f = i*256 + tid;             // 0..2047
                    int row = f >> 4, seg = f & 15;
                    int node = snode[row];
                    const uint32_t* base = g_means + (size_t)node*256 + (kb >> 5)*64;
                    if (seg < 8) {
                        cp_async16(sAhi_sh + row*144 + seg*16, base + seg*4);
                    } else {
                        int s2 = seg - 8;
                        cp_async16(sAlo_sh + row*144 + s2*16, base + 32 + s2*4);
                    }
                }
            } else {
                // ---- stage A: 128 rows x 32 k, fp32 -> tf32 hi/lo ----
                #pragma unroll
                for (int i = 0; i < 4; i++) {
                    int f = i*256 + tid;
                    int row = f >> 3, kc = (f & 7) * 4;
                    int node = snode[row];
                    float4 v = *(const float4*)(Asrc + (size_t)node*H + kb + kc);
                    uint32_t hi[4]; float lo[4];
                    float* e = &v.x;
                    #pragma unroll
                    for (int q = 0; q < 4; q++) {
                        hi[q] = f2tf32(e[q]);
                        lo[q] = e[q] - __uint_as_float(hi[q]);
                    }
                    int o = row*TS + kc;
                    *(uint4*)(sA_hi + o) = make_uint4(hi[0], hi[1], hi[2], hi[3]);
                    *(uint4*)(sA_lo + o) = make_uint4(f2tf32(lo[0]), f2tf32(lo[1]),
                                                      f2tf32(lo[2]), f2tf32(lo[3]));
                }
            }
            cp_async_commit_wait();
            __syncthreads();

            uint32_t* sW_hi = sW;
            uint32_t* sW_lo = sW + TILE_U32;

            // ---- MMA: warp covers rows [wid*16, wid*16+16) x cols [0,128) ----
            #pragma unroll
            for (int ks = 0; ks < 4; ks++) {
                int kk = ks*8 + lr;
                int row = wid*16 + lq;
                uint32_t a_hi[4], a_lo[4];
                a_hi[0] = sA_hi[row*TS + kk];
                a_hi[1] = sA_hi[(row+8)*TS + kk];
                a_hi[2] = sA_hi[row*TS + kk + 4];
                a_hi[3] = sA_hi[(row+8)*TS + kk + 4];
                a_lo[0] = sA_lo[row*TS + kk];
                a_lo[1] = sA_lo[(row+8)*TS + kk];
                a_lo[2] = sA_lo[row*TS + kk + 4];
                a_lo[3] = sA_lo[(row+8)*TS + kk + 4];
                #pragma unroll
                for (int nf = 0; nf < 16; nf++) {
                    int col = nf*8 + lq;
                    uint32_t b_hi[2], b_lo[2];
                    b_hi[0] = sW_hi[col*TS + kk];
                    b_hi[1] = sW_hi[col*TS + kk + 4];
                    b_lo[0] = sW_lo[col*TS + kk];
                    b_lo[1] = sW_lo[col*TS + kk + 4];
                    mma_tf32(d[nf], a_hi, b_hi);
                    mma_tf32(d[nf], a_lo, b_hi);
                    mma_tf32(d[nf], a_hi, b_lo);
                }
            }
        }
    }

    // ---- epilogue: bias + relu, write h, per-row deterministic score ----
    int r0 = wid*16 + lq;        // and r0+8
    int n0 = snode[r0], n1 = snode[r0+8];
    float* hp0 = g_h + (size_t)n0*H;
    float* hp1 = g_h + (size_t)n1*H;
    float s0 = 0.f, s1 = 0.f;
    #pragma unroll
    for (int nf = 0; nf < 16; nf++) {
        int col = nf*8 + lr*2;
        float w0 = swp[col], w1 = swp[col+1];
        float b0 = sb[col],  b1 = sb[col+1];
        float h00 = fmaxf(d[nf][0] + b0, 0.f);
        float h01 = fmaxf(d[nf][1] + b1, 0.f);
        float h10 = fmaxf(d[nf][2] + b0, 0.f);
        float h11 = fmaxf(d[nf][3] + b1, 0.f);
        s0 += h00*w0 + h01*w1;
        s1 += h10*w0 + h11*w1;
        *(float2*)(hp0 + col) = make_float2(h00, h01);
        *(float2*)(hp1 + col) = make_float2(h10, h11);
    }
    s0 += __shfl_xor_sync(0xFFFFFFFF, s0, 1);
    s0 += __shfl_xor_sync(0xFFFFFFFF, s0, 2);
    s1 += __shfl_xor_sync(0xFFFFFFFF, s1, 1);
    s1 += __shfl_xor_sync(0xFFFFFFFF, s1, 2);
    if (lr == 0) {
        g_score[n0] = s0;
        g_score[n1] = s1;
    }
}

// ---------------- per-graph top-k (1024 threads); gate selected x, ZERO pruned x ----------------
__global__ void k_topk(int livesel_in, int mlive, int kk, int livesel_out) {
    const int* live_in = (livesel_in == 1) ? g_liveA : (livesel_in == 2) ? g_liveB : nullptr;
    int* live_out = (livesel_out == 1) ? g_liveA : g_liveB;
    __shared__ unsigned long long keys[1024];
    __shared__ float gates[1024];
    int b = blockIdx.x;
    int tid = threadIdx.x;   // 1024 threads

    {
        unsigned long long key = 0xFFFFFFFFFFFFFFFFULL;
        if (tid < mlive) {
            int node = live_in ? live_in[b*NP + tid] : (b*NP + tid);
            unsigned int p = (unsigned int)(node - b*NP);
            float s = g_score[node];
            unsigned int u = __float_as_uint(s);
            u = (u & 0x80000000u) ? ~u : (u | 0x80000000u);
            key = (((unsigned long long)(~u)) << 32) | p;
        }
        keys[tid] = key;
    }
    __syncthreads();

    for (int k = 2; k <= 1024; k <<= 1) {
        for (int j = k >> 1; j > 0; j >>= 1) {
            int l = tid ^ j;
            if (l > tid) {
                bool asc = ((tid & k) == 0);
                unsigned long long a = keys[tid], c2 = keys[l];
                if ((a > c2) == asc) { keys[tid] = c2; keys[l] = a; }
            }
            __syncthreads();
        }
    }

    if (tid < NP) g_nm[b*NP + tid] = 0;
    __syncthreads();
    if (tid < kk) {
        unsigned int p = (unsigned int)(keys[tid] & 0xFFFFFFFFu);
        int node = b*NP + (int)p;
        g_nm[node] = 1;
        live_out[b*NP + tid] = node;
        gates[tid] = tanhf(g_score[node]);
    }
    __syncthreads();
    // gate selected rows
    for (int w = tid; w < kk*32; w += 1024) {
        int s = w >> 5, f = w & 31;
        unsigned int p = (unsigned int)(keys[s] & 0xFFFFFFFFu);
        int node = b*NP + (int)p;
        float4 hv = ((const float4*)(g_h + (size_t)node*H))[f];
        float g = gates[s];
        ((float4*)(g_x + (size_t)node*H))[f] =
            make_float4(hv.x*g, hv.y*g, hv.z*g, hv.w*g);
    }
    // zero rows alive-before-but-pruned-now so dense gathers stay exact
    int nz = mlive - kk;
    for (int w = tid; w < nz*32; w += 1024) {
        int s = kk + (w >> 5), f = w & 31;
        unsigned int p = (unsigned int)(keys[s] & 0xFFFFFFFFu);
        int node = b*NP + (int)p;
        ((float4*)(g_x + (size_t)node*H))[f] = make_float4(0.f, 0.f, 0.f, 0.f);
    }
}

// ---------------- mean pool + MLP + log_softmax (parallelized) ----------------
__global__ void k_mlp(int livesel, const float* __restrict__ Wf1, const float* __restrict__ bf1,
                      const float* __restrict__ Wf2, const float* __restrict__ bf2,
                      float* __restrict__ out) {
    const int* live = (livesel == 1) ? g_liveA : g_liveB;
    __shared__ float pool4[4][128];
    __shared__ float pooled[128];
    __shared__ float h1p[8][64];
    __shared__ float h1[64];
    __shared__ float o10[10];
    int b = blockIdx.x, tid = threadIdx.x;   // 512 threads
    int d = tid & 127, q = tid >> 7;          // q in 0..3
    float s = 0.f;
    for (int i = q; i < K3; i += 4) {
        int node = live[b*NP + i];
        s += g_x[(size_t)node*H + d];
    }
    pool4[q][d] = s;
    __syncthreads();
    if (tid < 128) {
        pooled[tid] = (pool4[0][tid] + pool4[1][tid] + pool4[2][tid] + pool4[3][tid])
                      * (1.0f/(float)K3);
    }
    __syncthreads();
    {
        int dd = tid & 63, qq = tid >> 6;     // qq in 0..7, 16 k's each
        float a = 0.f;
        #pragma unroll
        for (int k = 0; k < 16; k++)
            a += pooled[qq*16 + k] * Wf1[dd*128 + qq*16 + k];
        h1p[qq][dd] = a;
    }
    __syncthreads();
    if (tid < 64) {
        float a = bf1[tid];
        #pragma unroll
        for (int qq = 0; qq < 8; qq++) a += h1p[qq][tid];
        h1[tid] = fmaxf(a, 0.f);
    }
    __syncthreads();
    if (tid < 10) {
        float a = bf2[tid];
        for (int k = 0; k < 64; k++) a += h1[k] * Wf2[tid*64 + k];
        o10[tid] = a;
    }
    __syncthreads();
    if (tid == 0) {
        float m = -1e30f;
        for (int c = 0; c < C; c++) m = fmaxf(m, o10[c]);
        float se = 0.f;
        for (int c = 0; c < C; c++) se += expf(o10[c] - m);
        float lse = m + logf(se);
        for (int c = 0; c < C; c++) out[b*C + c] = o10[c] - lse;
    }
}

// ---------------- launch ----------------
extern "C" void kernel_launch(void* const* d_in, const int* in_sizes, int n_in,
                              void* d_out, int out_size) {
    const float* x   = (const float*)d_in[0];
    const int*   ei  = (const int*)  d_in[1];
    const float* Wl1 = (const float*)d_in[2];
    const float* bl1 = (const float*)d_in[3];
    const float* Wr1 = (const float*)d_in[4];
    const float* wp1 = (const float*)d_in[5];
    const float* Wl2 = (const float*)d_in[6];
    const float* bl2 = (const float*)d_in[7];
    const float* Wr2 = (const float*)d_in[8];
    const float* wp2 = (const float*)d_in[9];
    const float* Wl3 = (const float*)d_in[10];
    const float* bl3 = (const float*)d_in[11];
    const float* Wr3 = (const float*)d_in[12];
    const float* wp3 = (const float*)d_in[13];
    const float* Wf1 = (const float*)d_in[14];
    const float* bf1 = (const float*)d_in[15];
    const float* Wf2 = (const float*)d_in[16];
    const float* bf2 = (const float*)d_in[17];
    float* out = (float*)d_out;

    const int* srcp = ei;
    const int* dstp = ei + NE;

    cudaFuncSetAttribute(k_gemm_mma, cudaFuncAttributeMaxDynamicSharedMemorySize, SMEM_GEMM);

    // CSR build + consolidated setup
    k_init   <<<(NN + 255)/256, 256>>>();
    k_count  <<<(NE + 255)/256, 256>>>(dstp);
    k_scan1  <<<128, 1024>>>();
    k_scan23 <<<128, 1024>>>();
    k_fill   <<<(NE + 255)/256, 256>>>(srcp, dstp);
    k_wsplit6<<<384, 256>>>(Wl1, Wr1, Wl2, Wr2, Wl3, Wr3);
    k_wpnorm3<<<3, 128>>>(wp1, wp2, wp3);

    // layer 1 (all nodes live): 1024 tiles
    k_agg     <<<(NN*32 + 255)/256, 256>>>(0, 1, NN, x);
    k_gemm_mma<<<NN/128, 256, SMEM_GEMM>>>(0, 1, 0, x, bl1, wp1);
    k_topk    <<<B, 1024>>>(0, NP, K1, 1);

    // layer 2 (live list A, K1 per graph): 820 tiles
    {
        int M = B * K1;
        k_agg     <<<(M*32 + 255)/256, 256>>>(1, K1, M, x);
        k_gemm_mma<<<M/128, 256, SMEM_GEMM>>>(1, K1, 1, x, bl2, wp2);
        k_topk    <<<B, 1024>>>(1, K1, K2, 2);
    }

    // layer 3 (live list B, K2 per graph): 656 tiles
    {
        int M = B * K2;
        k_agg     <<<(M*32 + 255)/256, 256>>>(2, K2, M, x);
        k_gemm_mma<<<M/128, 256, SMEM_GEMM>>>(2, K2, 2, x, bl3, wp3);
        k_topk    <<<B, 1024>>>(2, K2, K3, 1);
    }

    // pool + MLP + log_softmax
    k_mlp<<<B, 512>>>(1, Wf1, bf1, Wf2, bf2, out);
}